// round 10
// baseline (speedup 1.0000x reference)
#include <cuda_runtime.h>
#include <cstdint>
#include <cstddef>

#define NB    1024
#define CIN   384
#define HWSZ  361
#define HWP   384
#define WST   100              // W row stride (floats)
#define KT    16
#define NT    (CIN / KT)       // 24

// float offsets in dynamic smem
#define OFF_W    0             // [384][100]
#define OFF_X    38400         // [2][16][384]
#define OFF_M    50688         // [384]
#define OFF_PS   51072         // [8][48]
#define OFF_PM   51456         // [8][48]
#define OFF_GP   51840         // [144]
#define OFF_HV   51984         // [48]
#define OFF_AV   52032         // [48]
#define OFF_WC   52080         // [96]
#define OFF_PV   52176         // [2]
#define OFF_BETA 52178         // [48]
#define SMEM_FLOATS 52226
#define SMEM_BYTES  (SMEM_FLOATS * 4)

typedef unsigned long long ull;

__device__ __forceinline__ ull pack2(float lo, float hi) {
    ull r; asm("mov.b64 %0, {%1,%2};" : "=l"(r) : "f"(lo), "f"(hi)); return r;
}
__device__ __forceinline__ float2 unpack2(ull v) {
    float2 r; asm("mov.b64 {%0,%1}, %2;" : "=f"(r.x), "=f"(r.y) : "l"(v)); return r;
}
__device__ __forceinline__ ull fma2(ull a, ull b, ull c) {
    ull d; asm("fma.rn.f32x2 %0, %1, %2, %3;" : "=l"(d) : "l"(a), "l"(b), "l"(c)); return d;
}
__device__ __forceinline__ uint32_t smem_u32(const void* p) {
    uint32_t a;
    asm("{ .reg .u64 t; cvta.to.shared.u64 t, %1; cvt.u32.u64 %0, t; }" : "=r"(a) : "l"(p));
    return a;
}
__device__ __forceinline__ void cp4(uint32_t dst, const void* src, uint32_t ssz) {
    asm volatile("cp.async.ca.shared.global [%0], [%1], 4, %2;"
                 :: "r"(dst), "l"(src), "r"(ssz) : "memory");
}
__device__ __forceinline__ void cp_commit() {
    asm volatile("cp.async.commit_group;" ::: "memory");
}

// ---------------------------------------------------------------------------
// 512 threads per CTA, one CTA per batch n.
// Block tile 96p x 384hw. Warps: pr = warp>>3 (2 p-rows of 48), wcol = warp&7
// (8 hw-cols of 48). Thread: ty = lane>>2 (8), tx = lane&3 (4);
// thread tile 6p x 12hw -> 36 ull accumulators.
// X staged via 4-byte cp.async (global rows are only 4B-aligned!).
// ---------------------------------------------------------------------------
extern "C" __global__ void __launch_bounds__(512, 1)
k_policy(const float* __restrict__ x, const float* __restrict__ mask,
         const float* __restrict__ msum,
         const float* __restrict__ w1p, const float* __restrict__ w1g,
         const float* __restrict__ betag,
         const float* __restrict__ wling, const float* __restrict__ wlinp,
         const float* __restrict__ blinp, const float* __restrict__ wlinp2,
         const float* __restrict__ beta2, const float* __restrict__ wc2,
         float* __restrict__ out)
{
    extern __shared__ float smem[];
    float* Wsm = smem + OFF_W;
    float* Xsm = smem + OFF_X;
    float* Msm = smem + OFF_M;
    float* ps  = smem + OFF_PS;
    float* pm  = smem + OFF_PM;
    float* gp  = smem + OFF_GP;
    float* hv  = smem + OFF_HV;
    float* av  = smem + OFF_AV;
    float* wcs = smem + OFF_WC;
    float* pv  = smem + OFF_PV;
    float* bts = smem + OFF_BETA;

    const int n    = blockIdx.x;
    const int tid  = threadIdx.x;
    const int warp = tid >> 5;
    const int lane = tid & 31;
    const int pr   = warp >> 3;          // 0: p 0..47, 1: p 48..95 (g)
    const int wcol = warp & 7;           // hw col of 48
    const int ty   = lane >> 2;          // 0..7  (p sub, 6 wide)
    const int tx   = lane & 3;           // 0..3  (hw sub, 12 wide)

    const float* xn = x + (size_t)n * CIN * HWSZ;
    const uint32_t xs_sa = smem_u32(Xsm);

    // ---- X tile staging: 4-byte cp.async, 12 per thread, coalesced ----
    // thread covers 12 consecutive floats starting at tid*12 within the
    // KT*HWP = 6144-element tile (6144 = 512*12).
    auto stage = [&](int t) {
        const int k0 = t * KT;
        const uint32_t base = xs_sa + (uint32_t)(t & 1) * (KT * HWP * 4);
        const int i0 = tid * 12;
        #pragma unroll
        for (int j = 0; j < 12; j++) {
            const int i   = i0 + j;
            const int row = i / HWP;
            const int col = i - row * HWP;
            const float* src = xn + (size_t)(k0 + row) * HWSZ + ((col < HWSZ) ? col : 0);
            cp4(base + (uint32_t)i * 4, src, (col < HWSZ) ? 4u : 0u);
        }
        cp_commit();
    };

    stage(0);
    stage(1);

    // ---- stage W transposed: Wsm[c][p], coalesced LDG, 4-way STS conflicts ----
    for (int i = tid; i < 96 * CIN; i += 512) {
        const int p = i / CIN, c = i % CIN;
        float v = (p < 48) ? w1p[p * CIN + c] : w1g[(p - 48) * CIN + c];
        Wsm[c * WST + p] = v;
    }
    if (tid < 48)  bts[tid] = betag[tid];
    if (tid < 96)  wcs[tid] = wc2[tid];
    if (tid < HWP) Msm[tid] = (tid < HWSZ) ? mask[n * HWSZ + tid] : 0.0f;
    __syncthreads();

    ull acc[6][6];
    #pragma unroll
    for (int i = 0; i < 6; i++)
        #pragma unroll
        for (int j = 0; j < 6; j++) acc[i][j] = 0ull;

    const float* wkb = Wsm + pr * 48 + ty * 6;
    const float* xkb = Xsm + wcol * 48 + tx * 12;

    for (int t = 0; t < NT; t++) {
        if (t == NT - 1) asm volatile("cp.async.wait_group 0;" ::: "memory");
        else             asm volatile("cp.async.wait_group 1;" ::: "memory");
        __syncthreads();

        const float* wt = wkb + (t * KT) * WST;
        const float* xt = xkb + (t & 1) * (KT * HWP);
        #pragma unroll 4
        for (int kk = 0; kk < KT; kk++) {
            const float2* ap = (const float2*)(wt + kk * WST);
            const ulonglong2* bp = (const ulonglong2*)(xt + kk * HWP);
            float2 A01 = ap[0], A23 = ap[1], A45 = ap[2];
            ulonglong2 q0 = bp[0], q1 = bp[1], q2 = bp[2];
            ull b0 = q0.x, b1 = q0.y, b2 = q1.x, b3 = q1.y, b4 = q2.x, b5 = q2.y;
            #define STEP(AV, I) { ull apk = pack2(AV, AV); \
                acc[I][0] = fma2(apk, b0, acc[I][0]); \
                acc[I][1] = fma2(apk, b1, acc[I][1]); \
                acc[I][2] = fma2(apk, b2, acc[I][2]); \
                acc[I][3] = fma2(apk, b3, acc[I][3]); \
                acc[I][4] = fma2(apk, b4, acc[I][4]); \
                acc[I][5] = fma2(apk, b5, acc[I][5]); }
            STEP(A01.x, 0)  STEP(A01.y, 1)
            STEP(A23.x, 2)  STEP(A23.y, 3)
            STEP(A45.x, 4)  STEP(A45.y, 5)
            #undef STEP
        }
        __syncthreads();
        if (t + 2 < NT) stage(t + 2);
    }

    // thread's 12 mask values
    float mv[12];
    {
        const float4* mp = (const float4*)(Msm + wcol * 48 + tx * 12);
        float4 m0 = mp[0], m1 = mp[1], m2 = mp[2];
        mv[0]=m0.x; mv[1]=m0.y; mv[2]=m0.z;  mv[3]=m0.w;
        mv[4]=m1.x; mv[5]=m1.y; mv[6]=m1.z;  mv[7]=m1.w;
        mv[8]=m2.x; mv[9]=m2.y; mv[10]=m2.z; mv[11]=m2.w;
    }

    // ---- g-pool: pr==1 warps ----
    if (pr == 1) {
        #pragma unroll
        for (int pi = 0; pi < 6; pi++) {
            const int g = ty * 6 + pi;
            const float b = bts[g];
            float s = 0.0f, mx = -3.0e38f;
            #pragma unroll
            for (int hj = 0; hj < 6; hj++) {
                float2 v = unpack2(acc[pi][hj]);
                float u0 = fmaxf((v.x + b) * mv[2*hj],   0.0f);
                float u1 = fmaxf((v.y + b) * mv[2*hj+1], 0.0f);
                s += u0 + u1;
                mx = fmaxf(mx, fmaxf(u0 + mv[2*hj] - 1.0f, u1 + mv[2*hj+1] - 1.0f));
            }
            s  += __shfl_down_sync(0xffffffffu, s, 2);
            mx  = fmaxf(mx, __shfl_down_sync(0xffffffffu, mx, 2));
            s  += __shfl_down_sync(0xffffffffu, s, 1);
            mx  = fmaxf(mx, __shfl_down_sync(0xffffffffu, mx, 1));
            if (tx == 0) { ps[wcol * 48 + g] = s; pm[wcol * 48 + g] = mx; }
        }
    }
    __syncthreads();

    // ---- pooled features ----
    const float ms = msum[n];
    if (tid < 48) {
        float s = 0.0f, mx = -3.0e38f;
        #pragma unroll
        for (int w = 0; w < 8; w++) {
            s  += ps[w * 48 + tid];
            mx  = fmaxf(mx, pm[w * 48 + tid]);
        }
        float mean = s / ms;
        gp[tid]      = mean;
        gp[48 + tid] = mean * (sqrtf(ms) - 14.0f) * 0.1f;
        gp[96 + tid] = mx;
    }
    __syncthreads();

    // ---- tiny FCs ----
    if (tid < 48) {
        float d1 = 0.0f, d2 = 0.0f;
        const float* wp  = wlinp + tid * 144;
        const float* wgr = wling + tid * 144;
        #pragma unroll 8
        for (int j = 0; j < 144; j++) {
            float g = gp[j];
            d1 += g * wp[j];
            d2 += g * wgr[j];
        }
        hv[tid] = fmaxf(d1 + blinp[tid], 0.0f);
        av[tid] = d2 + beta2[tid];
    }
    __syncthreads();
    if (tid < 2) {
        float p = 0.0f;
        const float* w2 = wlinp2 + tid * 48;
        #pragma unroll
        for (int i = 0; i < 48; i++) p += hv[i] * w2[i];
        pv[tid] = p;
    }
    __syncthreads();

    // ---- p-epilogue: pr==0 warps; reduce over ty (p), write 12 hw each ----
    float* on = out + (size_t)n * 6 * 362;
    if (pr == 0) {
        float a0[12], a1[12];
        #pragma unroll
        for (int h = 0; h < 12; h++) { a0[h] = 0.0f; a1[h] = 0.0f; }
        #pragma unroll
        for (int pi = 0; pi < 6; pi++) {
            const int p = ty * 6 + pi;
            const float ad = av[p];
            const float w0 = wcs[p];
            const float w1 = wcs[48 + p];
            #pragma unroll
            for (int hj = 0; hj < 6; hj++) {
                float2 v = unpack2(acc[pi][hj]);
                float u0 = fmaxf((v.x + ad) * mv[2*hj],   0.0f);
                float u1 = fmaxf((v.y + ad) * mv[2*hj+1], 0.0f);
                a0[2*hj]   += u0 * w0;  a1[2*hj]   += u0 * w1;
                a0[2*hj+1] += u1 * w0;  a1[2*hj+1] += u1 * w1;
            }
        }
        #pragma unroll
        for (int h = 0; h < 12; h++) {
            a0[h] += __shfl_down_sync(0xffffffffu, a0[h], 16);
            a1[h] += __shfl_down_sync(0xffffffffu, a1[h], 16);
            a0[h] += __shfl_down_sync(0xffffffffu, a0[h], 8);
            a1[h] += __shfl_down_sync(0xffffffffu, a1[h], 8);
            a0[h] += __shfl_down_sync(0xffffffffu, a0[h], 4);
            a1[h] += __shfl_down_sync(0xffffffffu, a1[h], 4);
        }
        if (ty == 0) {
            #pragma unroll
            for (int h = 0; h < 12; h++) {
                const int hw = wcol * 48 + tx * 12 + h;
                if (hw < HWSZ) {
                    float pen = (1.0f - mv[h]) * 5000.0f;
                    on[hw]           = a0[h] - pen;
                    on[5 * 362 + hw] = a1[h] - pen;
                }
            }
        }
    }
    if (tid == 0) {
        on[361]           = pv[0];
        on[5 * 362 + 361] = pv[1];
    }
    for (int i = tid; i < 4 * 362; i += 512) on[362 + i] = 0.0f;
}

// ---------------------------------------------------------------------------
extern "C" void kernel_launch(void* const* d_in, const int* in_sizes, int n_in,
                              void* d_out, int out_size)
{
    const float* x      = (const float*)d_in[0];
    const float* mask   = (const float*)d_in[1];
    const float* msum   = (const float*)d_in[2];
    const float* w1p    = (const float*)d_in[3];
    const float* w1g    = (const float*)d_in[4];
    const float* betag  = (const float*)d_in[5];
    const float* wling  = (const float*)d_in[6];
    const float* wlinp  = (const float*)d_in[7];
    const float* blinp  = (const float*)d_in[8];
    const float* wlinp2 = (const float*)d_in[9];
    const float* beta2  = (const float*)d_in[10];
    const float* wc2    = (const float*)d_in[11];
    float* out = (float*)d_out;

    cudaFuncSetAttribute(k_policy,
                         cudaFuncAttributeMaxDynamicSharedMemorySize, SMEM_BYTES);

    k_policy<<<NB, 512, SMEM_BYTES>>>(x, mask, msum, w1p, w1g, betag,
                                      wling, wlinp, blinp, wlinp2, beta2, wc2, out);
}

// round 11
// speedup vs baseline: 1.2847x; 1.2847x over previous
#include <cuda_runtime.h>
#include <cstdint>
#include <cstddef>

#define NB    1024
#define CIN   384
#define HWSZ  361
#define HWP   384              // padded hw
#define WST   100              // W row stride (floats), 400B, 16B-aligned
#define KT    16               // k per tile
#define NT    (CIN / KT)       // 24 tiles

// float offsets in dynamic smem
#define OFF_W    0                       // [384][100]
#define OFF_X    38400                   // [2][16][384]
#define OFF_M    50688                   // [384] mask (padded)
#define OFF_PS   51072                   // [6][48]
#define OFF_PM   51360                   // [6][48]
#define OFF_GP   51648                   // [144]
#define OFF_HV   51792                   // [48]
#define OFF_AV   51840                   // [48]
#define OFF_WC   51888                   // [96]
#define OFF_PV   51984                   // [2]
#define OFF_BETA 51986                   // [48]
#define SMEM_FLOATS 52036
#define SMEM_BYTES  (SMEM_FLOATS * 4)

typedef unsigned long long ull;

__device__ __forceinline__ ull pack2(float lo, float hi) {
    ull r; asm("mov.b64 %0, {%1,%2};" : "=l"(r) : "f"(lo), "f"(hi)); return r;
}
__device__ __forceinline__ float2 unpack2(ull v) {
    float2 r; asm("mov.b64 {%0,%1}, %2;" : "=f"(r.x), "=f"(r.y) : "l"(v)); return r;
}
__device__ __forceinline__ ull fma2(ull a, ull b, ull c) {
    ull d; asm("fma.rn.f32x2 %0, %1, %2, %3;" : "=l"(d) : "l"(a), "l"(b), "l"(c)); return d;
}
__device__ __forceinline__ uint32_t smem_u32(const void* p) {
    uint32_t a;
    asm("{ .reg .u64 t; cvta.to.shared.u64 t, %1; cvt.u32.u64 %0, t; }" : "=r"(a) : "l"(p));
    return a;
}
__device__ __forceinline__ void cp4(uint32_t dst, const void* src, uint32_t sz) {
    asm volatile("cp.async.ca.shared.global [%0], [%1], 4, %2;"
                 :: "r"(dst), "l"(src), "r"(sz) : "memory");
}
__device__ __forceinline__ void cp_commit() {
    asm volatile("cp.async.commit_group;" ::: "memory");
}

// ---------------------------------------------------------------------------
// One CTA (384 thr) per batch n. Register-tiled SGEMM with explicit
// register double-buffering of smem fragments:
//   block 96p x 384hw, warp 48p x 64hw (2 x 6 warps), thread 12p x 8hw.
// ---------------------------------------------------------------------------
extern "C" __global__ void __launch_bounds__(384, 1)
k_policy(const float* __restrict__ x, const float* __restrict__ mask,
         const float* __restrict__ msum,
         const float* __restrict__ w1p, const float* __restrict__ w1g,
         const float* __restrict__ betag,
         const float* __restrict__ wling, const float* __restrict__ wlinp,
         const float* __restrict__ blinp, const float* __restrict__ wlinp2,
         const float* __restrict__ beta2, const float* __restrict__ wc2,
         float* __restrict__ out)
{
    extern __shared__ float smem[];
    float* Wsm  = smem + OFF_W;
    float* Xsm  = smem + OFF_X;
    float* Msm  = smem + OFF_M;
    float* ps   = smem + OFF_PS;
    float* pm   = smem + OFF_PM;
    float* gp   = smem + OFF_GP;
    float* hv   = smem + OFF_HV;
    float* av   = smem + OFF_AV;
    float* wcs  = smem + OFF_WC;
    float* pv   = smem + OFF_PV;
    float* bts  = smem + OFF_BETA;

    const int n    = blockIdx.x;
    const int tid  = threadIdx.x;
    const int warp = tid >> 5;
    const int lane = tid & 31;
    const int wr   = warp / 6;          // 0: p-chans 0..47, 1: g-chans
    const int wc   = warp % 6;          // hw block of 64
    const int tx   = lane & 7;          // hw sub (8 wide)
    const int ty   = lane >> 3;         // p sub (12 wide)

    const float* xn = x + (size_t)n * CIN * HWSZ;
    const uint32_t xs_sa = smem_u32(Xsm);

    const int crow = tid / 96;                   // 0..3
    const int ccol = (tid % 96) * 4;             // 0..380

    // prologue: issue tiles 0 and 1
    #pragma unroll
    for (int t = 0; t < 2; t++) {
        #pragma unroll
        for (int i = 0; i < 4; i++) {
            const int k = t * KT + crow + 4 * i;
            const uint32_t dst = xs_sa + ((t & 1) * (KT * HWP) + (crow + 4 * i) * HWP + ccol) * 4;
            const float* src = xn + (size_t)k * HWSZ + ccol;
            #pragma unroll
            for (int j = 0; j < 4; j++)
                cp4(dst + 4 * j, src + j, (ccol + j < HWSZ) ? 4u : 0u);
        }
        cp_commit();
    }

    // ---- stage W transposed: Wsm[k][p], thread owns column c = tid ----
    {
        const int c = tid;
        float* wrow = Wsm + c * WST;
        #pragma unroll 4
        for (int p = 0; p < 96; p++)
            wrow[p] = (p < 48) ? w1p[p * CIN + c] : w1g[(p - 48) * CIN + c];
    }
    if (tid < 48)  bts[tid] = betag[tid];
    if (tid < 96)  wcs[tid] = wc2[tid];
    if (tid < HWP) Msm[tid] = (tid < HWSZ) ? mask[n * HWSZ + tid] : 0.0f;
    __syncthreads();

    ull acc[12][4];
    #pragma unroll
    for (int i = 0; i < 12; i++)
        #pragma unroll
        for (int j = 0; j < 4; j++) acc[i][j] = 0ull;

    const float* wkb = Wsm + wr * 48 + ty * 12;
    const float* xkb = Xsm + wc * 64 + tx * 8;

    // ---- main loop over 24 k-tiles, register-double-buffered fragments ----
    for (int t = 0; t < NT; t++) {
        if (t == NT - 1) asm volatile("cp.async.wait_group 0;" ::: "memory");
        else             asm volatile("cp.async.wait_group 1;" ::: "memory");
        __syncthreads();

        const float* wt = wkb + (t * KT) * WST;
        const float* xt = xkb + (t & 1) * (KT * HWP);

        float4 A0, A1, A2;
        ulonglong2 B0, B1;
        {
            const float4* ap = (const float4*)wt;
            const ulonglong2* bp = (const ulonglong2*)xt;
            A0 = ap[0]; A1 = ap[1]; A2 = ap[2];
            B0 = bp[0]; B1 = bp[1];
        }

        #pragma unroll
        for (int kk = 0; kk < KT; kk++) {
            float4 nA0 = A0, nA1 = A1, nA2 = A2;
            ulonglong2 nB0 = B0, nB1 = B1;
            if (kk + 1 < KT) {
                const float4* ap = (const float4*)(wt + (kk + 1) * WST);
                const ulonglong2* bp = (const ulonglong2*)(xt + (kk + 1) * HWP);
                nA0 = ap[0]; nA1 = ap[1]; nA2 = ap[2];
                nB0 = bp[0]; nB1 = bp[1];
            }
            ull b0 = B0.x, b1 = B0.y, b2 = B1.x, b3 = B1.y;
            #define STEP(AV, IDX) { ull apk = pack2(AV, AV); \
                acc[IDX][0] = fma2(apk, b0, acc[IDX][0]); \
                acc[IDX][1] = fma2(apk, b1, acc[IDX][1]); \
                acc[IDX][2] = fma2(apk, b2, acc[IDX][2]); \
                acc[IDX][3] = fma2(apk, b3, acc[IDX][3]); }
            STEP(A0.x, 0)  STEP(A0.y, 1)  STEP(A0.z, 2)  STEP(A0.w, 3)
            STEP(A1.x, 4)  STEP(A1.y, 5)  STEP(A1.z, 6)  STEP(A1.w, 7)
            STEP(A2.x, 8)  STEP(A2.y, 9)  STEP(A2.z, 10) STEP(A2.w, 11)
            #undef STEP
            A0 = nA0; A1 = nA1; A2 = nA2;
            B0 = nB0; B1 = nB1;
        }
        __syncthreads();

        if (t + 2 < NT) {
            const int tn = t + 2;
            #pragma unroll
            for (int i = 0; i < 4; i++) {
                const int k = tn * KT + crow + 4 * i;
                const uint32_t dst = xs_sa + ((tn & 1) * (KT * HWP) + (crow + 4 * i) * HWP + ccol) * 4;
                const float* src = xn + (size_t)k * HWSZ + ccol;
                #pragma unroll
                for (int j = 0; j < 4; j++)
                    cp4(dst + 4 * j, src + j, (ccol + j < HWSZ) ? 4u : 0u);
            }
            cp_commit();
        }
    }

    // thread's 8 mask values
    float mv[8];
    {
        const float4* mp = (const float4*)(Msm + wc * 64 + tx * 8);
        float4 m0 = mp[0], m1 = mp[1];
        mv[0]=m0.x; mv[1]=m0.y; mv[2]=m0.z; mv[3]=m0.w;
        mv[4]=m1.x; mv[5]=m1.y; mv[6]=m1.z; mv[7]=m1.w;
    }

    // ---- g-pool: wr==1 warps reduce their 12 g x 8 hw ----
    if (wr == 1) {
        #pragma unroll
        for (int pp = 0; pp < 12; pp++) {
            const int g = ty * 12 + pp;
            const float b = bts[g];
            float s = 0.0f, mx = -3.0e38f;
            #pragma unroll
            for (int hp = 0; hp < 4; hp++) {
                float2 v = unpack2(acc[pp][hp]);
                float u0 = fmaxf((v.x + b) * mv[2*hp],   0.0f);
                float u1 = fmaxf((v.y + b) * mv[2*hp+1], 0.0f);
                s += u0 + u1;
                mx = fmaxf(mx, fmaxf(u0 + mv[2*hp] - 1.0f, u1 + mv[2*hp+1] - 1.0f));
            }
            s  += __shfl_down_sync(0xffffffffu, s, 4);
            mx  = fmaxf(mx, __shfl_down_sync(0xffffffffu, mx, 4));
            s  += __shfl_down_sync(0xffffffffu, s, 2);
            mx  = fmaxf(mx, __shfl_down_sync(0xffffffffu, mx, 2));
            s  += __shfl_down_sync(0xffffffffu, s, 1);
            mx  = fmaxf(mx, __shfl_down_sync(0xffffffffu, mx, 1));
            if (tx == 0) { ps[wc * 48 + g] = s; pm[wc * 48 + g] = mx; }
        }
    }
    __syncthreads();

    // ---- pooled features ----
    const float ms = msum[n];
    if (tid < 48) {
        float s = 0.0f, mx = -3.0e38f;
        #pragma unroll
        for (int w = 0; w < 6; w++) {
            s  += ps[w * 48 + tid];
            mx  = fmaxf(mx, pm[w * 48 + tid]);
        }
        float mean = s / ms;
        gp[tid]      = mean;
        gp[48 + tid] = mean * (sqrtf(ms) - 14.0f) * 0.1f;
        gp[96 + tid] = mx;
    }
    __syncthreads();

    // ---- tiny FCs ----
    if (tid < 48) {
        float d1 = 0.0f, d2 = 0.0f;
        const float* wp  = wlinp + tid * 144;
        const float* wgr = wling + tid * 144;
        #pragma unroll 8
        for (int j = 0; j < 144; j++) {
            float g = gp[j];
            d1 += g * wp[j];
            d2 += g * wgr[j];
        }
        hv[tid] = fmaxf(d1 + blinp[tid], 0.0f);
        av[tid] = d2 + beta2[tid];
    }
    __syncthreads();
    if (tid < 2) {
        float p = 0.0f;
        const float* w2 = wlinp2 + tid * 48;
        #pragma unroll
        for (int i = 0; i < 48; i++) p += hv[i] * w2[i];
        pv[tid] = p;
    }
    __syncthreads();

    // ---- p-epilogue: wr==0 warps, cross-ty reduce, write 2 channels ----
    float* on = out + (size_t)n * 6 * 362;
    if (wr == 0) {
        float a0[8], a1[8];
        #pragma unroll
        for (int h = 0; h < 8; h++) { a0[h] = 0.0f; a1[h] = 0.0f; }
        #pragma unroll
        for (int pp = 0; pp < 12; pp++) {
            const int p = ty * 12 + pp;
            const float ad = av[p];
            const float w0 = wcs[p];
            const float w1 = wcs[48 + p];
            #pragma unroll
            for (int hp = 0; hp < 4; hp++) {
                float2 v = unpack2(acc[pp][hp]);
                float u0 = fmaxf((v.x + ad) * mv[2*hp],   0.0f);
                float u1 = fmaxf((v.y + ad) * mv[2*hp+1], 0.0f);
                a0[2*hp]   += u0 * w0;  a1[2*hp]   += u0 * w1;
                a0[2*hp+1] += u1 * w0;  a1[2*hp+1] += u1 * w1;
            }
        }
        #pragma unroll
        for (int h = 0; h < 8; h++) {
            a0[h] += __shfl_down_sync(0xffffffffu, a0[h], 16);
            a1[h] += __shfl_down_sync(0xffffffffu, a1[h], 16);
            a0[h] += __shfl_down_sync(0xffffffffu, a0[h], 8);
            a1[h] += __shfl_down_sync(0xffffffffu, a1[h], 8);
        }
        if (ty == 0) {
            #pragma unroll
            for (int h = 0; h < 8; h++) {
                const int hw = wc * 64 + tx * 8 + h;
                if (hw < HWSZ) {
                    float pen = (1.0f - mv[h]) * 5000.0f;
                    on[hw]           = a0[h] - pen;
                    on[5 * 362 + hw] = a1[h] - pen;
                }
            }
        }
    }
    if (tid == 0) {
        on[361]           = pv[0];
        on[5 * 362 + 361] = pv[1];
    }
    for (int i = tid; i < 4 * 362; i += 384) on[362 + i] = 0.0f;
}

// ---------------------------------------------------------------------------
extern "C" void kernel_launch(void* const* d_in, const int* in_sizes, int n_in,
                              void* d_out, int out_size)
{
    const float* x      = (const float*)d_in[0];
    const float* mask   = (const float*)d_in[1];
    const float* msum   = (const float*)d_in[2];
    const float* w1p    = (const float*)d_in[3];
    const float* w1g    = (const float*)d_in[4];
    const float* betag  = (const float*)d_in[5];
    const float* wling  = (const float*)d_in[6];
    const float* wlinp  = (const float*)d_in[7];
    const float* blinp  = (const float*)d_in[8];
    const float* wlinp2 = (const float*)d_in[9];
    const float* beta2  = (const float*)d_in[10];
    const float* wc2    = (const float*)d_in[11];
    float* out = (float*)d_out;

    cudaFuncSetAttribute(k_policy,
                         cudaFuncAttributeMaxDynamicSharedMemorySize, SMEM_BYTES);

    k_policy<<<NB, 384, SMEM_BYTES>>>(x, mask, msum, w1p, w1g, betag,
                                      wling, wlinp, blinp, wlinp2, beta2, wc2, out);
}

// round 13
// speedup vs baseline: 1.4464x; 1.1259x over previous
#include <cuda_runtime.h>
#include <cstdint>
#include <cstddef>

#define NB    1024
#define CIN   384
#define HWSZ  361
#define XST   392              // X smem row stride (floats): banks spread
#define KT    16               // k per staged tile
#define NT    (CIN / KT)       // 24 tiles
#define XTILE (KT * XST)       // 6272 floats per X buffer

// float offsets in dynamic smem
#define OFF_WF   0             // [48 k8][6 pt][32 lane][4]  = 36864
#define OFF_X    36864         // [2][16][392]               = 12544
#define OFF_M    49408         // [384]
#define OFF_PS   49792         // [4][48]
#define OFF_PM   49984         // [4][48]
#define OFF_PA0  50176         // [2][384]
#define OFF_PA1  50944         // [2][384]
#define OFF_GP   51712         // [144]
#define OFF_HV   51856         // [48]
#define OFF_AV   51904         // [48]
#define OFF_WC   51952         // [96]
#define OFF_PV   52048         // [2]
#define OFF_BETA 52050         // [48]
#define SMEM_FLOATS 52098
#define SMEM_BYTES  (SMEM_FLOATS * 4)

__device__ __forceinline__ uint32_t smem_u32(const void* p) {
    uint32_t a;
    asm("{ .reg .u64 t; cvta.to.shared.u64 t, %1; cvt.u32.u64 %0, t; }" : "=r"(a) : "l"(p));
    return a;
}
__device__ __forceinline__ void cp4(uint32_t dst, const void* src, uint32_t sz) {
    asm volatile("cp.async.ca.shared.global [%0], [%1], 4, %2;"
                 :: "r"(dst), "l"(src), "r"(sz) : "memory");
}
__device__ __forceinline__ void cp_commit() {
    asm volatile("cp.async.commit_group;" ::: "memory");
}
__device__ __forceinline__ uint32_t tf32hi(float v) {
    uint32_t r; asm("cvt.rna.tf32.f32 %0, %1;" : "=r"(r) : "f"(v)); return r;
}
__device__ __forceinline__ void mma8(float* d, const uint32_t* a, uint32_t b0, uint32_t b1) {
    asm volatile(
        "mma.sync.aligned.m16n8k8.row.col.f32.tf32.tf32.f32 "
        "{%0,%1,%2,%3}, {%4,%5,%6,%7}, {%8,%9}, {%0,%1,%2,%3};"
        : "+f"(d[0]), "+f"(d[1]), "+f"(d[2]), "+f"(d[3])
        : "r"(a[0]), "r"(a[1]), "r"(a[2]), "r"(a[3]), "r"(b0), "r"(b1));
}

// ---------------------------------------------------------------------------
// One CTA (384 thr, 12 warps) per batch n. 3xTF32 mma.sync GEMM:
//   D[96p, 384hw] = W[96, 384k] * X[384k, 384hw]
//   warp tile 32p x 96hw: p0 = (w%3)*32, hw0 = (w/3)*96
//   per warp: 2 A-tiles (m16) x 12 B-tiles (n8), acc[2][12][4] fp32.
// W pre-swizzled into per-fragment order (1 LDS.128 per A frag).
// ---------------------------------------------------------------------------
extern "C" __global__ void __launch_bounds__(384, 1)
k_policy(const float* __restrict__ x, const float* __restrict__ mask,
         const float* __restrict__ msum,
         const float* __restrict__ w1p, const float* __restrict__ w1g,
         const float* __restrict__ betag,
         const float* __restrict__ wling, const float* __restrict__ wlinp,
         const float* __restrict__ blinp, const float* __restrict__ wlinp2,
         const float* __restrict__ beta2, const float* __restrict__ wc2,
         float* __restrict__ out)
{
    extern __shared__ float smem[];
    float* Wf  = smem + OFF_WF;
    float* Xsm = smem + OFF_X;
    float* Msm = smem + OFF_M;
    float* ps  = smem + OFF_PS;
    float* pm  = smem + OFF_PM;
    float* pa0 = smem + OFF_PA0;
    float* pa1 = smem + OFF_PA1;
    float* gp  = smem + OFF_GP;
    float* hv  = smem + OFF_HV;
    float* av  = smem + OFF_AV;
    float* wcs = smem + OFF_WC;
    float* pv  = smem + OFF_PV;
    float* bts = smem + OFF_BETA;

    const int n    = blockIdx.x;
    const int tid  = threadIdx.x;
    const int warp = tid >> 5;
    const int lane = tid & 31;
    const int gid  = lane >> 2;          // 0..7
    const int tig  = lane & 3;           // 0..3
    const int pr   = warp % 3;           // p block: p0 = pr*32
    const int wb   = warp / 3;           // hw block: hw0 = wb*96
    const int p0   = pr * 32;
    const int hw0  = wb * 96;

    const float* xn = x + (size_t)n * CIN * HWSZ;
    const uint32_t xs_sa = smem_u32(Xsm);

    // ---- X tile staging: thread owns column tid, copies 16 rows ----
    auto stage = [&](int t) {
        const int k0 = t * KT;
        const uint32_t base = xs_sa + (uint32_t)(t & 1) * (XTILE * 4);
        const bool ok = (tid < HWSZ);
        const float* src = xn + (size_t)k0 * HWSZ + (ok ? tid : 0);
        #pragma unroll
        for (int r = 0; r < KT; r++)
            cp4(base + (uint32_t)(r * XST + tid) * 4, src + r * HWSZ, ok ? 4u : 0u);
        cp_commit();
    };

    stage(0);
    stage(1);

    // ---- W fragment staging: Wf[k8][pt][lane][e] ----
    for (int idx = tid; idx < 36864; idx += 384) {
        const int e  = idx & 3;
        const int ln = (idx >> 2) & 31;
        const int v  = idx >> 7;
        const int pt = v % 6;
        const int k8 = v / 6;
        const int p  = pt * 16 + (ln >> 2) + (e & 1) * 8;
        const int k  = k8 * 8 + (ln & 3) + (e >> 1) * 4;
        Wf[idx] = (p < 48) ? w1p[p * CIN + k] : w1g[(p - 48) * CIN + k];
    }
    if (tid < 48)  bts[tid] = betag[tid];
    if (tid < 96)  wcs[tid] = wc2[tid];
    Msm[tid] = (tid < HWSZ) ? mask[n * HWSZ + tid] : 0.0f;
    __syncthreads();

    float acc[2][12][4];
    #pragma unroll
    for (int a = 0; a < 2; a++)
        #pragma unroll
        for (int t2 = 0; t2 < 12; t2++)
            #pragma unroll
            for (int e = 0; e < 4; e++) acc[a][t2][e] = 0.0f;

    const int off_b = tig * XST + hw0 + gid;     // B frag base (b0); b1 = +4*XST
    const float4* wf4 = (const float4*)Wf;

    // ---- main loop: 24 staged tiles x 2 k8-steps ----
    for (int t = 0; t < NT; t++) {
        if (t == NT - 1) asm volatile("cp.async.wait_group 0;" ::: "memory");
        else             asm volatile("cp.async.wait_group 1;" ::: "memory");
        __syncthreads();

        const float* xb = Xsm + (t & 1) * XTILE;
        #pragma unroll
        for (int ks = 0; ks < 2; ks++) {
            const int k8 = t * 2 + ks;
            // A fragments: hi/lo tf32
            uint32_t Ah[2][4], Al[2][4];
            #pragma unroll
            for (int at = 0; at < 2; at++) {
                float4 w4 = wf4[(k8 * 6 + pr * 2 + at) * 32 + lane];
                const float wv[4] = {w4.x, w4.y, w4.z, w4.w};
                #pragma unroll
                for (int e = 0; e < 4; e++) {
                    uint32_t h = tf32hi(wv[e]);
                    Ah[at][e] = h;
                    Al[at][e] = tf32hi(wv[e] - __uint_as_float(h));
                }
            }
            const float* xk = xb + ks * 8 * XST + off_b;
            #pragma unroll
            for (int nt = 0; nt < 12; nt++) {
                float b0f = xk[nt * 8];
                float b1f = xk[nt * 8 + 4 * XST];
                uint32_t bh0 = tf32hi(b0f);
                uint32_t bh1 = tf32hi(b1f);
                uint32_t bl0 = tf32hi(b0f - __uint_as_float(bh0));
                uint32_t bl1 = tf32hi(b1f - __uint_as_float(bh1));
                mma8(acc[0][nt], Ah[0], bh0, bh1);
                mma8(acc[1][nt], Ah[1], bh0, bh1);
                mma8(acc[0][nt], Al[0], bh0, bh1);
                mma8(acc[1][nt], Al[1], bh0, bh1);
                mma8(acc[0][nt], Ah[0], bl0, bl1);
                mma8(acc[1][nt], Ah[1], bl0, bl1);
            }
        }
        __syncthreads();
        if (t + 2 < NT) stage(t + 2);
    }

    // ---- g-pool: rows p >= 48 ----
    #pragma unroll
    for (int at = 0; at < 2; at++) {
        #pragma unroll
        for (int rh = 0; rh < 2; rh++) {
            const int pbase = p0 + at * 16 + rh * 8;
            if (pbase >= 48) {                       // uniform per warp
                const int g = pbase - 48 + gid;
                const float b = bts[g];
                float s = 0.0f, mx = -3.0e38f;
                #pragma unroll
                for (int nt = 0; nt < 12; nt++) {
                    #pragma unroll
                    for (int c = 0; c < 2; c++) {
                        const float m = Msm[hw0 + nt * 8 + 2 * tig + c];
                        const float d = acc[at][nt][rh * 2 + c];
                        const float u = fmaxf((d + b) * m, 0.0f);
                        s += u;
                        mx = fmaxf(mx, u + m - 1.0f);
                    }
                }
                s  += __shfl_down_sync(0xffffffffu, s, 2);
                mx  = fmaxf(mx, __shfl_down_sync(0xffffffffu, mx, 2));
                s  += __shfl_down_sync(0xffffffffu, s, 1);
                mx  = fmaxf(mx, __shfl_down_sync(0xffffffffu, mx, 1));
                if (tig == 0) { ps[wb * 48 + g] = s; pm[wb * 48 + g] = mx; }
            }
        }
    }
    __syncthreads();

    // ---- pooled features ----
    const float ms = msum[n];
    if (tid < 48) {
        float s = 0.0f, mx = -3.0e38f;
        #pragma unroll
        for (int w = 0; w < 4; w++) {
            s  += ps[w * 48 + tid];
            mx  = fmaxf(mx, pm[w * 48 + tid]);
        }
        float mean = s / ms;
        gp[tid]      = mean;
        gp[48 + tid] = mean * (sqrtf(ms) - 14.0f) * 0.1f;
        gp[96 + tid] = mx;
    }
    __syncthreads();

    // ---- tiny FCs ----
    if (tid < 48) {
        float d1 = 0.0f, d2 = 0.0f;
        const float* wp  = wlinp + tid * 144;
        const float* wgr = wling + tid * 144;
        #pragma unroll 8
        for (int j = 0; j < 144; j++) {
            float g = gp[j];
            d1 += g * wp[j];
            d2 += g * wgr[j];
        }
        hv[tid] = fmaxf(d1 + blinp[tid], 0.0f);
        av[tid] = d2 + beta2[tid];
    }
    __syncthreads();
    if (tid < 2) {
        float p = 0.0f;
        const float* w2 = wlinp2 + tid * 48;
        #pragma unroll
        for (int i = 0; i < 48; i++) p += hv[i] * w2[i];
        pv[tid] = p;
    }
    __syncthreads();

    // ---- p-epilogue partials: rows p < 48 (warps pr 0,1) ----
    if (pr < 2) {
        #pragma unroll
        for (int nt = 0; nt < 12; nt++) {
            #pragma unroll
            for (int c = 0; c < 2; c++) {
                const int col = hw0 + nt * 8 + 2 * tig + c;
                const float m = Msm[col];
                float a0 = 0.0f, a1 = 0.0f;
                #pragma unroll
                for (int at = 0; at < 2; at++) {
                    #pragma unroll
                    for (int rh = 0; rh < 2; rh++) {
                        const int pbase = p0 + at * 16 + rh * 8;
                        if (pbase < 48) {            // uniform per warp
                            const int p = pbase + gid;
                            const float d = acc[at][nt][rh * 2 + c];
                            const float u = fmaxf((d + av[p]) * m, 0.0f);
                            a0 += u * wcs[p];
                            a1 += u * wcs[48 + p];
                        }
                    }
                }
                a0 += __shfl_down_sync(0xffffffffu, a0, 16);
                a1 += __shfl_down_sync(0xffffffffu, a1, 16);
                a0 += __shfl_down_sync(0xffffffffu, a0, 8);
                a1 += __shfl_down_sync(0xffffffffu, a1, 8);
                a0 += __shfl_down_sync(0xffffffffu, a0, 4);
                a1 += __shfl_down_sync(0xffffffffu, a1, 4);
                if (gid == 0) {
                    pa0[pr * 384 + col] = a0;
                    pa1[pr * 384 + col] = a1;
                }
            }
        }
    }
    __syncthreads();

    // ---- final output ----
    float* on = out + (size_t)n * 6 * 362;
    if (tid < HWSZ) {
        const float m = Msm[tid];
        const float pen = (1.0f - m) * 5000.0f;
        on[tid]           = pa0[tid] + pa0[384 + tid] - pen;
        on[5 * 362 + tid] = pa1[tid] + pa1[384 + tid] - pen;
    } else if (tid == HWSZ) {
        on[361]           = pv[0];
        on[5 * 362 + 361] = pv[1];
    }
    for (int i = tid; i < 4 * 362; i += 384) on[362 + i] = 0.0f;
}

// ---------------------------------------------------------------------------
extern "C" void kernel_launch(void* const* d_in, const int* in_sizes, int n_in,
                              void* d_out, int out_size)
{
    const float* x      = (const float*)d_in[0];
    const float* mask   = (const float*)d_in[1];
    const float* msum   = (const float*)d_in[2];
    const float* w1p    = (const float*)d_in[3];
    const float* w1g    = (const float*)d_in[4];
    const float* betag  = (const float*)d_in[5];
    const float* wling  = (const float*)d_in[6];
    const float* wlinp  = (const float*)d_in[7];
    const float* blinp  = (const float*)d_in[8];
    const float* wlinp2 = (const float*)d_in[9];
    const float* beta2  = (const float*)d_in[10];
    const float* wc2    = (const float*)d_in[11];
    float* out = (float*)d_out;

    cudaFuncSetAttribute(k_policy,
                         cudaFuncAttributeMaxDynamicSharedMemorySize, SMEM_BYTES);

    k_policy<<<NB, 384, SMEM_BYTES>>>(x, mask, msum, w1p, w1g, betag,
                                      wling, wlinp, blinp, wlinp2, beta2, wc2, out);
}